// round 1
// baseline (speedup 1.0000x reference)
#include <cuda_runtime.h>
#include <cuda_bf16.h>

// Problem constants (fixed by setup_inputs)
#define BATCH 4
#define IMG 256
#define WS 8
#define NW 1024              // (256/8)^2
#define BWIN (BATCH * NW)    // 4096 windows
#define NTOK 64              // WS*WS
#define CH 256
#define HEADS 8
#define HD 32
#define MTOT (BWIN * NTOK)   // 262144 rows

// Scratch (device globals are the sanctioned scratch mechanism)
__device__ float g_Q[(size_t)MTOT * CH];
__device__ float g_K[(size_t)MTOT * CH];
__device__ float g_V[(size_t)MTOT * CH];
__device__ float g_S[(size_t)MTOT * CH];

// ---------------------------------------------------------------------------
// GEMM: C[M x 256] = A[M x 256] @ Wt^T + bias, Wt is (256 out, 256 in) row-major
// Tile 128x128x16, 256 threads, 8x8 per thread.
// ---------------------------------------------------------------------------
__global__ __launch_bounds__(256) void gemm_kernel(
    const float* __restrict__ A, const float* __restrict__ Wt,
    const float* __restrict__ bias, float* __restrict__ C)
{
    __shared__ float As[16][128];
    __shared__ float Bs[16][128];

    const int t  = threadIdx.x;
    const int m0 = blockIdx.y * 128;
    const int n0 = blockIdx.x * 128;
    const int tx = t & 15;       // n-tile
    const int ty = t >> 4;       // m-tile

    float acc[8][8];
#pragma unroll
    for (int i = 0; i < 8; i++)
#pragma unroll
        for (int j = 0; j < 8; j++) acc[i][j] = 0.f;

    for (int kc = 0; kc < 256; kc += 16) {
        __syncthreads();
        // load 128x16 of A and of Wt (2 float4 per thread each)
#pragma unroll
        for (int it = 0; it < 2; it++) {
            int idx = t + it * 256;            // 0..511
            int row = idx >> 2;                // 0..127
            int kk  = (idx & 3) << 2;          // 0,4,8,12
            float4 a4 = *(const float4*)(A  + (size_t)(m0 + row) * 256 + kc + kk);
            As[kk + 0][row] = a4.x; As[kk + 1][row] = a4.y;
            As[kk + 2][row] = a4.z; As[kk + 3][row] = a4.w;
            float4 b4 = *(const float4*)(Wt + (size_t)(n0 + row) * 256 + kc + kk);
            Bs[kk + 0][row] = b4.x; Bs[kk + 1][row] = b4.y;
            Bs[kk + 2][row] = b4.z; Bs[kk + 3][row] = b4.w;
        }
        __syncthreads();
#pragma unroll
        for (int k = 0; k < 16; k++) {
            float a[8], b[8];
            *(float4*)(a)     = *(const float4*)&As[k][ty * 8];
            *(float4*)(a + 4) = *(const float4*)&As[k][ty * 8 + 4];
            *(float4*)(b)     = *(const float4*)&Bs[k][tx * 8];
            *(float4*)(b + 4) = *(const float4*)&Bs[k][tx * 8 + 4];
#pragma unroll
            for (int i = 0; i < 8; i++)
#pragma unroll
                for (int j = 0; j < 8; j++) acc[i][j] = fmaf(a[i], b[j], acc[i][j]);
        }
    }

    float bv[8];
#pragma unroll
    for (int j = 0; j < 8; j++) bv[j] = bias[n0 + tx * 8 + j];

#pragma unroll
    for (int i = 0; i < 8; i++) {
        int m = m0 + ty * 8 + i;
        float* crow = C + (size_t)m * 256 + n0 + tx * 8;
        float4 v0 = make_float4(acc[i][0] + bv[0], acc[i][1] + bv[1],
                                acc[i][2] + bv[2], acc[i][3] + bv[3]);
        float4 v1 = make_float4(acc[i][4] + bv[4], acc[i][5] + bv[5],
                                acc[i][6] + bv[6], acc[i][7] + bv[7]);
        *(float4*)crow       = v0;
        *((float4*)crow + 1) = v1;
    }
}

// ---------------------------------------------------------------------------
// Attention: one block per (window b, head h). N=64 tokens, hd=32.
// S[b, n, h*32+d] = softmax(scale*Q K^T + mask) @ V
// ---------------------------------------------------------------------------
__global__ __launch_bounds__(256) void attn_kernel(
    const float* __restrict__ Q, const float* __restrict__ K,
    const float* __restrict__ V, const float* __restrict__ mask,
    float* __restrict__ S)
{
    __shared__ float Qst[32][65];   // [d][n], padded
    __shared__ float Kst[32][65];
    __shared__ float Vs[64][32];    // [m][d]
    __shared__ float P[64][64];     // scores / probs

    const int h = blockIdx.x;       // 0..7
    const int b = blockIdx.y;       // 0..4095
    const int t = threadIdx.x;      // 256

    const size_t base = ((size_t)b * NTOK) * CH + h * HD;
    const float scale = 0.17677669529663687f; // 32^-0.5

    // load Q (scaled, transposed), K (transposed), V
#pragma unroll
    for (int it = 0; it < 2; it++) {
        int idx = t + it * 256;            // 0..511
        int row = idx >> 3;                // token 0..63
        int d4  = (idx & 7) * 4;           // 0..28
        float4 q4 = *(const float4*)(Q + base + (size_t)row * 256 + d4);
        float4 k4 = *(const float4*)(K + base + (size_t)row * 256 + d4);
        float4 v4 = *(const float4*)(V + base + (size_t)row * 256 + d4);
        Qst[d4 + 0][row] = q4.x * scale; Qst[d4 + 1][row] = q4.y * scale;
        Qst[d4 + 2][row] = q4.z * scale; Qst[d4 + 3][row] = q4.w * scale;
        Kst[d4 + 0][row] = k4.x; Kst[d4 + 1][row] = k4.y;
        Kst[d4 + 2][row] = k4.z; Kst[d4 + 3][row] = k4.w;
        *(float4*)&Vs[row][d4] = v4;
    }
    __syncthreads();

    // scores: 16x16 thread grid, 4x4 per thread
    {
        const int tx = t & 15, ty = t >> 4;
        float c[4][4];
#pragma unroll
        for (int i = 0; i < 4; i++)
#pragma unroll
            for (int j = 0; j < 4; j++) c[i][j] = 0.f;
#pragma unroll
        for (int d = 0; d < 32; d++) {
            float a[4], bb[4];
#pragma unroll
            for (int i = 0; i < 4; i++) a[i]  = Qst[d][ty * 4 + i];
#pragma unroll
            for (int j = 0; j < 4; j++) bb[j] = Kst[d][tx * 4 + j];
#pragma unroll
            for (int i = 0; i < 4; i++)
#pragma unroll
                for (int j = 0; j < 4; j++) c[i][j] = fmaf(a[i], bb[j], c[i][j]);
        }
        const float* mp = mask + (size_t)(b & (NW - 1)) * NTOK * NTOK;
#pragma unroll
        for (int i = 0; i < 4; i++)
#pragma unroll
            for (int j = 0; j < 4; j++)
                P[ty * 4 + i][tx * 4 + j] = c[i][j] + mp[(ty * 4 + i) * 64 + tx * 4 + j];
    }
    __syncthreads();

    // softmax: warp w owns rows w*8..w*8+7; lane handles cols lane, lane+32
    {
        const int warp = t >> 5, lane = t & 31;
#pragma unroll
        for (int r = 0; r < 8; r++) {
            int row = warp * 8 + r;
            float v0 = P[row][lane], v1 = P[row][lane + 32];
            float mx = fmaxf(v0, v1);
#pragma unroll
            for (int o = 16; o; o >>= 1) mx = fmaxf(mx, __shfl_xor_sync(0xffffffffu, mx, o));
            float e0 = __expf(v0 - mx), e1 = __expf(v1 - mx);
            float sm = e0 + e1;
#pragma unroll
            for (int o = 16; o; o >>= 1) sm += __shfl_xor_sync(0xffffffffu, sm, o);
            float inv = 1.f / sm;
            P[row][lane] = e0 * inv;
            P[row][lane + 32] = e1 * inv;
        }
    }
    __syncthreads();

    // O = P @ V: thread (d = t&31, n0 = t>>5), rows n0 + 8r
    {
        const int d = t & 31, n0 = t >> 5;
        float o[8];
#pragma unroll
        for (int r = 0; r < 8; r++) o[r] = 0.f;
        for (int m = 0; m < 64; m++) {
            float vv = Vs[m][d];
#pragma unroll
            for (int r = 0; r < 8; r++) o[r] = fmaf(P[n0 + r * 8][m], vv, o[r]);
        }
#pragma unroll
        for (int r = 0; r < 8; r++)
            S[base + (size_t)(n0 + r * 8) * 256 + d] = o[r];
    }
}

// ---------------------------------------------------------------------------
// LePE: depthwise 3x3 conv over window-reversed Q, accumulated into g_S.
// grid: (win 0..1023, b 0..3, cchunk 0..3); block 256 thr = 4 spatial x 64 ch
// ---------------------------------------------------------------------------
__global__ __launch_bounds__(256) void lepe_kernel(
    const float* __restrict__ Q, const float* __restrict__ rw,
    const float* __restrict__ rb, float* __restrict__ S)
{
    __shared__ float sm[100][64];   // 10x10 halo tile x 64 channels

    const int win = blockIdx.x;             // wr*32 + wc
    const int b   = blockIdx.y;
    const int cb  = blockIdx.z * 64;
    const int wr = win >> 5, wc = win & 31;
    const int hh0 = wr * 8, ww0 = wc * 8;
    const int t = threadIdx.x;
    const int c = t & 63, p0 = t >> 6;      // p0 in 0..3

    for (int p = p0; p < 100; p += 4) {
        int py = p / 10, px = p % 10;
        int hh = hh0 + py - 1, ww = ww0 + px - 1;
        float v = 0.f;
        if (hh >= 0 && hh < IMG && ww >= 0 && ww < IMG) {
            size_t idx = (((size_t)(b * NW + (hh >> 3) * 32 + (ww >> 3))) * NTOK
                          + ((hh & 7) * 8 + (ww & 7))) * (size_t)CH + cb + c;
            v = Q[idx];
        }
        sm[p][c] = v;
    }
    __syncthreads();

    float w[9];
#pragma unroll
    for (int k = 0; k < 9; k++) w[k] = rw[(cb + c) * 9 + k];
    const float bias = rb[cb + c];

    const size_t sbase = (((size_t)(b * NW + win)) * NTOK) * CH + cb + c;
    for (int p = p0; p < 64; p += 4) {
        int py = p >> 3, px = p & 7;
        float acc = bias;
#pragma unroll
        for (int dy = 0; dy < 3; dy++)
#pragma unroll
            for (int dx = 0; dx < 3; dx++)
                acc = fmaf(sm[(py + dy) * 10 + (px + dx)][c], w[dy * 3 + dx], acc);
        S[sbase + (size_t)p * CH] += acc;
    }
}

// ---------------------------------------------------------------------------
// kernel_launch
// inputs: x, y, mask, Wq, bq, Wk, bk, Wv, bv, rpe_w, rpe_b, Wp, bp, B, H, W
// ---------------------------------------------------------------------------
extern "C" void kernel_launch(void* const* d_in, const int* in_sizes, int n_in,
                              void* d_out, int out_size)
{
    const float* x    = (const float*)d_in[0];
    const float* y    = (const float*)d_in[1];
    const float* mask = (const float*)d_in[2];
    const float* Wq   = (const float*)d_in[3];
    const float* bq   = (const float*)d_in[4];
    const float* Wk   = (const float*)d_in[5];
    const float* bk   = (const float*)d_in[6];
    const float* Wv   = (const float*)d_in[7];
    const float* bv   = (const float*)d_in[8];
    const float* rw   = (const float*)d_in[9];
    const float* rb   = (const float*)d_in[10];
    const float* Wp   = (const float*)d_in[11];
    const float* bp   = (const float*)d_in[12];
    float* out        = (float*)d_out;

    float *pQ, *pK, *pV, *pS;
    cudaGetSymbolAddress((void**)&pQ, g_Q);
    cudaGetSymbolAddress((void**)&pK, g_K);
    cudaGetSymbolAddress((void**)&pV, g_V);
    cudaGetSymbolAddress((void**)&pS, g_S);

    dim3 gg(2, MTOT / 128);   // (256/128, 262144/128)
    gemm_kernel<<<gg, 256>>>(x, Wq, bq, pQ);
    gemm_kernel<<<gg, 256>>>(y, Wk, bk, pK);
    gemm_kernel<<<gg, 256>>>(x, Wv, bv, pV);

    attn_kernel<<<dim3(HEADS, BWIN), 256>>>(pQ, pK, pV, mask, pS);

    lepe_kernel<<<dim3(NW, BATCH, 4), 256>>>(pQ, rw, rb, pS);

    gemm_kernel<<<gg, 256>>>(pS, Wp, bp, out);
}

// round 3
// speedup vs baseline: 2.0214x; 2.0214x over previous
#include <cuda_runtime.h>
#include <cuda_bf16.h>
#include <cstdint>

// Problem constants (fixed by setup_inputs)
#define BATCH 4
#define IMG 256
#define WS 8
#define NW 1024              // (256/8)^2
#define BWIN (BATCH * NW)    // 4096 windows
#define NTOK 64              // WS*WS
#define CH 256
#define HEADS 8
#define HD 32
#define MTOT (BWIN * NTOK)   // 262144 rows

// Scratch
__device__ float g_Q[(size_t)MTOT * CH];
__device__ float g_K[(size_t)MTOT * CH];
__device__ float g_V[(size_t)MTOT * CH];
__device__ float g_S[(size_t)MTOT * CH];

// ---------------------------------------------------------------------------
// tf32 helpers (sm_80-generic; compute_103-safe)
// ---------------------------------------------------------------------------
__device__ __forceinline__ uint32_t tf32_rna(float x) {
    uint32_t y;
    asm("cvt.rna.tf32.f32 %0, %1;" : "=r"(y) : "f"(x));
    return y;
}
__device__ __forceinline__ void mma_tf32(float* d, const uint32_t* a, const uint32_t* b) {
    asm volatile(
        "mma.sync.aligned.m16n8k8.row.col.f32.tf32.tf32.f32 "
        "{%0,%1,%2,%3}, {%4,%5,%6,%7}, {%8,%9}, {%0,%1,%2,%3};"
        : "+f"(d[0]), "+f"(d[1]), "+f"(d[2]), "+f"(d[3])
        : "r"(a[0]), "r"(a[1]), "r"(a[2]), "r"(a[3]), "r"(b[0]), "r"(b[1]));
}

// ---------------------------------------------------------------------------
// GEMM via mma.sync tf32: C[M x 256] = A[M x 256] @ Wt^T + bias
// Wt is (256 out, 256 in) row-major == .col B operand directly.
// Block 256 thr (8 warps, 2x4), tile 128x128x32, warp tile 64x32.
// ---------------------------------------------------------------------------
__global__ __launch_bounds__(256) void gemm_mma(
    const float* __restrict__ A, const float* __restrict__ Wt,
    const float* __restrict__ bias, float* __restrict__ C)
{
    __shared__ uint32_t As[128][36];   // [m][k] tf32 bits, pad 36 -> conflict-free frags
    __shared__ uint32_t Bs[128][36];   // [n][k]

    const int t = threadIdx.x, lane = t & 31, warp = t >> 5;
    const int wm = warp & 1, wn = warp >> 1;         // 2 x 4 warp grid
    const int m0 = blockIdx.y * 128, n0 = blockIdx.x * 128;
    const int g = lane >> 2, tg = lane & 3;

    float acc[4][4][4];
#pragma unroll
    for (int mi = 0; mi < 4; mi++)
#pragma unroll
        for (int ni = 0; ni < 4; ni++)
#pragma unroll
            for (int r = 0; r < 4; r++) acc[mi][ni][r] = 0.f;

    for (int kc = 0; kc < 256; kc += 32) {
        __syncthreads();
#pragma unroll
        for (int i = 0; i < 4; i++) {
            int idx = t + i * 256;           // 0..1023
            int row = idx >> 3;              // 0..127
            int c4 = (idx & 7) * 4;          // 0..28
            float4 a4 = *(const float4*)(A + (size_t)(m0 + row) * 256 + kc + c4);
            float4 b4 = *(const float4*)(Wt + (size_t)(n0 + row) * 256 + kc + c4);
            As[row][c4 + 0] = tf32_rna(a4.x); As[row][c4 + 1] = tf32_rna(a4.y);
            As[row][c4 + 2] = tf32_rna(a4.z); As[row][c4 + 3] = tf32_rna(a4.w);
            Bs[row][c4 + 0] = tf32_rna(b4.x); Bs[row][c4 + 1] = tf32_rna(b4.y);
            Bs[row][c4 + 2] = tf32_rna(b4.z); Bs[row][c4 + 3] = tf32_rna(b4.w);
        }
        __syncthreads();

#pragma unroll
        for (int ks = 0; ks < 4; ks++) {
            const int k0 = ks * 8;
            uint32_t a[4][4], b[4][2];
#pragma unroll
            for (int mi = 0; mi < 4; mi++) {
                int r = wm * 64 + mi * 16 + g;
                a[mi][0] = As[r][k0 + tg];
                a[mi][1] = As[r + 8][k0 + tg];
                a[mi][2] = As[r][k0 + tg + 4];
                a[mi][3] = As[r + 8][k0 + tg + 4];
            }
#pragma unroll
            for (int ni = 0; ni < 4; ni++) {
                int r = wn * 32 + ni * 8 + g;
                b[ni][0] = Bs[r][k0 + tg];
                b[ni][1] = Bs[r][k0 + tg + 4];
            }
#pragma unroll
            for (int mi = 0; mi < 4; mi++)
#pragma unroll
                for (int ni = 0; ni < 4; ni++)
                    mma_tf32(acc[mi][ni], a[mi], b[ni]);
        }
    }

    // Epilogue: c0/c1 at (row=g, col=2*tg), c2/c3 at (row=g+8, same cols)
    float bv[4][2];
#pragma unroll
    for (int ni = 0; ni < 4; ni++) {
        int col = n0 + wn * 32 + ni * 8 + 2 * tg;
        bv[ni][0] = __ldg(bias + col);
        bv[ni][1] = __ldg(bias + col + 1);
    }
#pragma unroll
    for (int mi = 0; mi < 4; mi++) {
        int r0 = m0 + wm * 64 + mi * 16 + g;
#pragma unroll
        for (int ni = 0; ni < 4; ni++) {
            int col = n0 + wn * 32 + ni * 8 + 2 * tg;
            float2 v0 = make_float2(acc[mi][ni][0] + bv[ni][0], acc[mi][ni][1] + bv[ni][1]);
            float2 v1 = make_float2(acc[mi][ni][2] + bv[ni][0], acc[mi][ni][3] + bv[ni][1]);
            *(float2*)(C + (size_t)r0 * 256 + col) = v0;
            *(float2*)(C + (size_t)(r0 + 8) * 256 + col) = v1;
        }
    }
}

// ---------------------------------------------------------------------------
// Attention: one block per (window b, head h). N=64 tokens, hd=32. (unchanged)
// ---------------------------------------------------------------------------
__global__ __launch_bounds__(256) void attn_kernel(
    const float* __restrict__ Q, const float* __restrict__ K,
    const float* __restrict__ V, const float* __restrict__ mask,
    float* __restrict__ S)
{
    __shared__ float Qst[32][65];
    __shared__ float Kst[32][65];
    __shared__ float Vs[64][32];
    __shared__ float P[64][64];

    const int h = blockIdx.x;
    const int b = blockIdx.y;
    const int t = threadIdx.x;

    const size_t base = ((size_t)b * NTOK) * CH + h * HD;
    const float scale = 0.17677669529663687f;

#pragma unroll
    for (int it = 0; it < 2; it++) {
        int idx = t + it * 256;
        int row = idx >> 3;
        int d4 = (idx & 7) * 4;
        float4 q4 = *(const float4*)(Q + base + (size_t)row * 256 + d4);
        float4 k4 = *(const float4*)(K + base + (size_t)row * 256 + d4);
        float4 v4 = *(const float4*)(V + base + (size_t)row * 256 + d4);
        Qst[d4 + 0][row] = q4.x * scale; Qst[d4 + 1][row] = q4.y * scale;
        Qst[d4 + 2][row] = q4.z * scale; Qst[d4 + 3][row] = q4.w * scale;
        Kst[d4 + 0][row] = k4.x; Kst[d4 + 1][row] = k4.y;
        Kst[d4 + 2][row] = k4.z; Kst[d4 + 3][row] = k4.w;
        *(float4*)&Vs[row][d4] = v4;
    }
    __syncthreads();

    {
        const int tx = t & 15, ty = t >> 4;
        float c[4][4];
#pragma unroll
        for (int i = 0; i < 4; i++)
#pragma unroll
            for (int j = 0; j < 4; j++) c[i][j] = 0.f;
#pragma unroll
        for (int d = 0; d < 32; d++) {
            float a[4], bb[4];
#pragma unroll
            for (int i = 0; i < 4; i++) a[i] = Qst[d][ty * 4 + i];
#pragma unroll
            for (int j = 0; j < 4; j++) bb[j] = Kst[d][tx * 4 + j];
#pragma unroll
            for (int i = 0; i < 4; i++)
#pragma unroll
                for (int j = 0; j < 4; j++) c[i][j] = fmaf(a[i], bb[j], c[i][j]);
        }
        const float* mp = mask + (size_t)(b & (NW - 1)) * NTOK * NTOK;
#pragma unroll
        for (int i = 0; i < 4; i++)
#pragma unroll
            for (int j = 0; j < 4; j++)
                P[ty * 4 + i][tx * 4 + j] = c[i][j] + mp[(ty * 4 + i) * 64 + tx * 4 + j];
    }
    __syncthreads();

    {
        const int warp = t >> 5, lane = t & 31;
#pragma unroll
        for (int r = 0; r < 8; r++) {
            int row = warp * 8 + r;
            float v0 = P[row][lane], v1 = P[row][lane + 32];
            float mx = fmaxf(v0, v1);
#pragma unroll
            for (int o = 16; o; o >>= 1) mx = fmaxf(mx, __shfl_xor_sync(0xffffffffu, mx, o));
            float e0 = __expf(v0 - mx), e1 = __expf(v1 - mx);
            float sm = e0 + e1;
#pragma unroll
            for (int o = 16; o; o >>= 1) sm += __shfl_xor_sync(0xffffffffu, sm, o);
            float inv = 1.f / sm;
            P[row][lane] = e0 * inv;
            P[row][lane + 32] = e1 * inv;
        }
    }
    __syncthreads();

    {
        const int d = t & 31, n0 = t >> 5;
        float o[8];
#pragma unroll
        for (int r = 0; r < 8; r++) o[r] = 0.f;
        for (int m = 0; m < 64; m++) {
            float vv = Vs[m][d];
#pragma unroll
            for (int r = 0; r < 8; r++) o[r] = fmaf(P[n0 + r * 8][m], vv, o[r]);
        }
#pragma unroll
        for (int r = 0; r < 8; r++)
            S[base + (size_t)(n0 + r * 8) * 256 + d] = o[r];
    }
}

// ---------------------------------------------------------------------------
// LePE depthwise 3x3 conv, accumulated into g_S. (unchanged)
// ---------------------------------------------------------------------------
__global__ __launch_bounds__(256) void lepe_kernel(
    const float* __restrict__ Q, const float* __restrict__ rw,
    const float* __restrict__ rb, float* __restrict__ S)
{
    __shared__ float sm[100][64];

    const int win = blockIdx.x;
    const int b = blockIdx.y;
    const int cb = blockIdx.z * 64;
    const int wr = win >> 5, wc = win & 31;
    const int hh0 = wr * 8, ww0 = wc * 8;
    const int t = threadIdx.x;
    const int c = t & 63, p0 = t >> 6;

    for (int p = p0; p < 100; p += 4) {
        int py = p / 10, px = p % 10;
        int hh = hh0 + py - 1, ww = ww0 + px - 1;
        float v = 0.f;
        if (hh >= 0 && hh < IMG && ww >= 0 && ww < IMG) {
            size_t idx = (((size_t)(b * NW + (hh >> 3) * 32 + (ww >> 3))) * NTOK
                          + ((hh & 7) * 8 + (ww & 7))) * (size_t)CH + cb + c;
            v = Q[idx];
        }
        sm[p][c] = v;
    }
    __syncthreads();

    float w[9];
#pragma unroll
    for (int k = 0; k < 9; k++) w[k] = rw[(cb + c) * 9 + k];
    const float bias = rb[cb + c];

    const size_t sbase = (((size_t)(b * NW + win)) * NTOK) * CH + cb + c;
    for (int p = p0; p < 64; p += 4) {
        int py = p >> 3, px = p & 7;
        float acc = bias;
#pragma unroll
        for (int dy = 0; dy < 3; dy++)
#pragma unroll
            for (int dx = 0; dx < 3; dx++)
                acc = fmaf(sm[(py + dy) * 10 + (px + dx)][c], w[dy * 3 + dx], acc);
        S[sbase + (size_t)p * CH] += acc;
    }
}

// ---------------------------------------------------------------------------
// kernel_launch
// ---------------------------------------------------------------------------
extern "C" void kernel_launch(void* const* d_in, const int* in_sizes, int n_in,
                              void* d_out, int out_size)
{
    const float* x    = (const float*)d_in[0];
    const float* y    = (const float*)d_in[1];
    const float* mask = (const float*)d_in[2];
    const float* Wq   = (const float*)d_in[3];
    const float* bq   = (const float*)d_in[4];
    const float* Wk   = (const float*)d_in[5];
    const float* bk   = (const float*)d_in[6];
    const float* Wv   = (const float*)d_in[7];
    const float* bv   = (const float*)d_in[8];
    const float* rw   = (const float*)d_in[9];
    const float* rb   = (const float*)d_in[10];
    const float* Wp   = (const float*)d_in[11];
    const float* bp   = (const float*)d_in[12];
    float* out        = (float*)d_out;

    float *pQ, *pK, *pV, *pS;
    cudaGetSymbolAddress((void**)&pQ, g_Q);
    cudaGetSymbolAddress((void**)&pK, g_K);
    cudaGetSymbolAddress((void**)&pV, g_V);
    cudaGetSymbolAddress((void**)&pS, g_S);

    dim3 gg(2, MTOT / 128);   // (256/128, 262144/128)
    gemm_mma<<<gg, 256>>>(x, Wq, bq, pQ);
    gemm_mma<<<gg, 256>>>(y, Wk, bk, pK);
    gemm_mma<<<gg, 256>>>(x, Wv, bv, pV);

    attn_kernel<<<dim3(HEADS, BWIN), 256>>>(pQ, pK, pV, mask, pS);

    lepe_kernel<<<dim3(NW, BATCH, 4), 256>>>(pQ, rw, rb, pS);

    gemm_mma<<<gg, 256>>>(pS, Wp, bp, out);
}

// round 4
// speedup vs baseline: 2.4964x; 1.2350x over previous
#include <cuda_runtime.h>
#include <cuda_bf16.h>
#include <cstdint>

// Problem constants (fixed by setup_inputs)
#define BATCH 4
#define IMG 256
#define WS 8
#define NW 1024              // (256/8)^2
#define BWIN (BATCH * NW)    // 4096 windows
#define NTOK 64              // WS*WS
#define CH 256
#define HEADS 8
#define HD 32
#define MTOT (BWIN * NTOK)   // 262144 rows

// Scratch
__device__ float g_Q[(size_t)MTOT * CH];
__device__ float g_K[(size_t)MTOT * CH];
__device__ float g_V[(size_t)MTOT * CH];
__device__ float g_S[(size_t)MTOT * CH];

// ---------------------------------------------------------------------------
// helpers (sm_80-generic; compute_103-safe)
// ---------------------------------------------------------------------------
__device__ __forceinline__ uint32_t tf32_rna(float x) {
    uint32_t y;
    asm("cvt.rna.tf32.f32 %0, %1;" : "=r"(y) : "f"(x));
    return y;
}
__device__ __forceinline__ void mma_tf32(float* d, const uint32_t* a, const uint32_t* b) {
    asm volatile(
        "mma.sync.aligned.m16n8k8.row.col.f32.tf32.tf32.f32 "
        "{%0,%1,%2,%3}, {%4,%5,%6,%7}, {%8,%9}, {%0,%1,%2,%3};"
        : "+f"(d[0]), "+f"(d[1]), "+f"(d[2]), "+f"(d[3])
        : "r"(a[0]), "r"(a[1]), "r"(a[2]), "r"(a[3]), "r"(b[0]), "r"(b[1]));
}
__device__ __forceinline__ uint32_t smem_u32(const void* p) {
    uint32_t a;
    asm("{ .reg .u64 t; cvta.to.shared.u64 t, %1; cvt.u32.u64 %0, t; }" : "=r"(a) : "l"(p));
    return a;
}
__device__ __forceinline__ void cp16(void* dst, const void* src) {
    uint32_t d = smem_u32(dst);
    asm volatile("cp.async.cg.shared.global [%0], [%1], 16;" :: "r"(d), "l"(src));
}
#define CP_COMMIT() asm volatile("cp.async.commit_group;" ::: "memory")
#define CP_WAIT1()  asm volatile("cp.async.wait_group 1;" ::: "memory")

// ---------------------------------------------------------------------------
// GEMM via mma.sync tf32, cp.async double-buffered:
// C[M x 256] = A[M x 256] @ Wt^T + bias
// Block 256 thr (8 warps, 2x4), tile 128x128x32, warp tile 64x32.
// ---------------------------------------------------------------------------
#define GP 36                               // fp32 row stride in smem (pad)
#define GEMM_SMEM (2 * 2 * 128 * GP * 4)    // 73728 B

__global__ __launch_bounds__(256) void gemm_mma(
    const float* __restrict__ A, const float* __restrict__ Wt,
    const float* __restrict__ bias, float* __restrict__ C)
{
    extern __shared__ float gsm[];
    float* As = gsm;                 // [2][128][GP]
    float* Bs = gsm + 2 * 128 * GP;  // [2][128][GP]

    const int t = threadIdx.x, lane = t & 31, warp = t >> 5;
    const int wm = warp & 1, wn = warp >> 1;         // 2 x 4 warp grid
    const int m0 = blockIdx.y * 128, n0 = blockIdx.x * 128;
    const int g = lane >> 2, tg = lane & 3;

    const int lrow = t >> 3;            // 0..31 (+32*i)
    const int lc4  = (t & 7) * 4;       // 0..28

    float acc[4][4][4];
#pragma unroll
    for (int mi = 0; mi < 4; mi++)
#pragma unroll
        for (int ni = 0; ni < 4; ni++)
#pragma unroll
            for (int r = 0; r < 4; r++) acc[mi][ni][r] = 0.f;

    // prologue: tile 0 -> buf 0
#pragma unroll
    for (int i = 0; i < 4; i++) {
        int row = lrow + i * 32;
        cp16(&As[row * GP + lc4], A  + (size_t)(m0 + row) * 256 + lc4);
        cp16(&Bs[row * GP + lc4], Wt + (size_t)(n0 + row) * 256 + lc4);
    }
    CP_COMMIT();

    for (int kc = 0; kc < 8; kc++) {
        if (kc < 7) {
            int buf = (kc + 1) & 1;
            int ko = (kc + 1) * 32;
#pragma unroll
            for (int i = 0; i < 4; i++) {
                int row = lrow + i * 32;
                cp16(&As[(buf * 128 + row) * GP + lc4], A  + (size_t)(m0 + row) * 256 + ko + lc4);
                cp16(&Bs[(buf * 128 + row) * GP + lc4], Wt + (size_t)(n0 + row) * 256 + ko + lc4);
            }
        }
        CP_COMMIT();
        CP_WAIT1();
        __syncthreads();

        const float* Ab = As + (kc & 1) * 128 * GP;
        const float* Bb = Bs + (kc & 1) * 128 * GP;
#pragma unroll
        for (int ks = 0; ks < 4; ks++) {
            const int k0 = ks * 8;
            uint32_t a[4][4], b[4][2];
#pragma unroll
            for (int mi = 0; mi < 4; mi++) {
                int r = wm * 64 + mi * 16 + g;
                a[mi][0] = tf32_rna(Ab[r * GP + k0 + tg]);
                a[mi][1] = tf32_rna(Ab[(r + 8) * GP + k0 + tg]);
                a[mi][2] = tf32_rna(Ab[r * GP + k0 + tg + 4]);
                a[mi][3] = tf32_rna(Ab[(r + 8) * GP + k0 + tg + 4]);
            }
#pragma unroll
            for (int ni = 0; ni < 4; ni++) {
                int r = wn * 32 + ni * 8 + g;
                b[ni][0] = tf32_rna(Bb[r * GP + k0 + tg]);
                b[ni][1] = tf32_rna(Bb[r * GP + k0 + tg + 4]);
            }
#pragma unroll
            for (int mi = 0; mi < 4; mi++)
#pragma unroll
                for (int ni = 0; ni < 4; ni++)
                    mma_tf32(acc[mi][ni], a[mi], b[ni]);
        }
        __syncthreads();
    }

    float bv[4][2];
#pragma unroll
    for (int ni = 0; ni < 4; ni++) {
        int col = n0 + wn * 32 + ni * 8 + 2 * tg;
        bv[ni][0] = __ldg(bias + col);
        bv[ni][1] = __ldg(bias + col + 1);
    }
#pragma unroll
    for (int mi = 0; mi < 4; mi++) {
        int r0 = m0 + wm * 64 + mi * 16 + g;
#pragma unroll
        for (int ni = 0; ni < 4; ni++) {
            int col = n0 + wn * 32 + ni * 8 + 2 * tg;
            *(float2*)(C + (size_t)r0 * 256 + col) =
                make_float2(acc[mi][ni][0] + bv[ni][0], acc[mi][ni][1] + bv[ni][1]);
            *(float2*)(C + (size_t)(r0 + 8) * 256 + col) =
                make_float2(acc[mi][ni][2] + bv[ni][0], acc[mi][ni][3] + bv[ni][1]);
        }
    }
}

// ---------------------------------------------------------------------------
// Attention via mma.sync tf32. Block = 128 thr (4 warps) per (window, head-pair).
// Warp w: head = hp*2 + (w>>1), rows 32*(w&1)..+31.
// smem: Qs/Ks/Vs [64][68] tf32 bits (head-pair channel slice), Ps [4][32][68].
// ---------------------------------------------------------------------------
#define AT 68
#define ATTN_SMEM ((3 * 64 * AT + 4 * 32 * AT) * 4)   // 87040 B

__global__ __launch_bounds__(128) void attn_mma(
    const float* __restrict__ Q, const float* __restrict__ K,
    const float* __restrict__ V, const float* __restrict__ mask,
    float* __restrict__ S)
{
    extern __shared__ uint32_t sm[];
    uint32_t* Qs = sm;                       // [64][AT]
    uint32_t* Ks = sm + 64 * AT;
    uint32_t* Vs = sm + 2 * 64 * AT;
    uint32_t* Ps = sm + 3 * 64 * AT;         // [4][32][AT]

    const int hp = blockIdx.x;      // 0..3 head-pair
    const int b  = blockIdx.y;      // 0..4095
    const int t = threadIdx.x, lane = t & 31, w = t >> 5;
    const int g = lane >> 2, tg = lane & 3;
    const size_t base = (size_t)b * NTOK * CH + hp * 64;
    const float scale = 0.17677669529663687f; // 32^-0.5

    // stage Q (scaled), K, V channel slice as tf32
#pragma unroll
    for (int i = 0; i < 8; i++) {
        int idx = i * 128 + t;
        int row = idx >> 4;            // 0..63
        int cq  = (idx & 15) * 4;      // 0..60
        const float4 q4 = *(const float4*)(Q + base + (size_t)row * 256 + cq);
        const float4 k4 = *(const float4*)(K + base + (size_t)row * 256 + cq);
        const float4 v4 = *(const float4*)(V + base + (size_t)row * 256 + cq);
        uint32_t* qp = Qs + row * AT + cq;
        qp[0] = tf32_rna(q4.x * scale); qp[1] = tf32_rna(q4.y * scale);
        qp[2] = tf32_rna(q4.z * scale); qp[3] = tf32_rna(q4.w * scale);
        uint32_t* kp = Ks + row * AT + cq;
        kp[0] = tf32_rna(k4.x); kp[1] = tf32_rna(k4.y);
        kp[2] = tf32_rna(k4.z); kp[3] = tf32_rna(k4.w);
        uint32_t* vp = Vs + row * AT + cq;
        vp[0] = tf32_rna(v4.x); vp[1] = tf32_rna(v4.y);
        vp[2] = tf32_rna(v4.z); vp[3] = tf32_rna(v4.w);
    }
    __syncthreads();

    const int ch0 = (w >> 1) * 32;    // head channel offset within slice
    const int rbase = (w & 1) * 32;   // token-row base

    // scores: acc[mi][ni][4], rows rbase+mi*16+{g,g+8}, cols ni*8+2tg+{0,1}
    float acc[2][8][4];
#pragma unroll
    for (int mi = 0; mi < 2; mi++)
#pragma unroll
        for (int ni = 0; ni < 8; ni++)
#pragma unroll
            for (int r = 0; r < 4; r++) acc[mi][ni][r] = 0.f;

#pragma unroll
    for (int ks = 0; ks < 4; ks++) {
        const int k0 = ch0 + ks * 8;
        uint32_t a[2][4], bb[8][2];
#pragma unroll
        for (int mi = 0; mi < 2; mi++) {
            int r = rbase + mi * 16 + g;
            a[mi][0] = Qs[r * AT + k0 + tg];
            a[mi][1] = Qs[(r + 8) * AT + k0 + tg];
            a[mi][2] = Qs[r * AT + k0 + tg + 4];
            a[mi][3] = Qs[(r + 8) * AT + k0 + tg + 4];
        }
#pragma unroll
        for (int ni = 0; ni < 8; ni++) {
            int r = ni * 8 + g;
            bb[ni][0] = Ks[r * AT + k0 + tg];
            bb[ni][1] = Ks[r * AT + k0 + tg + 4];
        }
#pragma unroll
        for (int mi = 0; mi < 2; mi++)
#pragma unroll
            for (int ni = 0; ni < 8; ni++)
                mma_tf32(acc[mi][ni], a[mi], bb[ni]);
    }

    // mask + softmax (register-resident, quad shuffles), write P to smem as tf32
    const float* mp = mask + (size_t)(b & (NW - 1)) * NTOK * NTOK;
#pragma unroll
    for (int mi = 0; mi < 2; mi++) {
#pragma unroll
        for (int half = 0; half < 2; half++) {
            const int row = rbase + mi * 16 + half * 8 + g;
            const int o = half * 2;
            float v[8][2];
            float mx = -1e30f;
#pragma unroll
            for (int ni = 0; ni < 8; ni++) {
                float2 mv = *(const float2*)(mp + row * 64 + ni * 8 + 2 * tg);
                v[ni][0] = acc[mi][ni][o] + mv.x;
                v[ni][1] = acc[mi][ni][o + 1] + mv.y;
                mx = fmaxf(mx, fmaxf(v[ni][0], v[ni][1]));
            }
            mx = fmaxf(mx, __shfl_xor_sync(0xffffffffu, mx, 1));
            mx = fmaxf(mx, __shfl_xor_sync(0xffffffffu, mx, 2));
            float sum = 0.f;
#pragma unroll
            for (int ni = 0; ni < 8; ni++) {
                v[ni][0] = __expf(v[ni][0] - mx);
                v[ni][1] = __expf(v[ni][1] - mx);
                sum += v[ni][0] + v[ni][1];
            }
            sum += __shfl_xor_sync(0xffffffffu, sum, 1);
            sum += __shfl_xor_sync(0xffffffffu, sum, 2);
            const float inv = 1.f / sum;
            uint32_t* pp = Ps + (w * 32 + mi * 16 + half * 8 + g) * AT;
#pragma unroll
            for (int ni = 0; ni < 8; ni++) {
                pp[ni * 8 + 2 * tg]     = tf32_rna(v[ni][0] * inv);
                pp[ni * 8 + 2 * tg + 1] = tf32_rna(v[ni][1] * inv);
            }
        }
    }
    __syncwarp();

    // O = P @ V  (k = 64 tokens, n = 32 channels)
    float acc2[2][4][4];
#pragma unroll
    for (int mi = 0; mi < 2; mi++)
#pragma unroll
        for (int ni = 0; ni < 4; ni++)
#pragma unroll
            for (int r = 0; r < 4; r++) acc2[mi][ni][r] = 0.f;

    const uint32_t* Pw = Ps + w * 32 * AT;
#pragma unroll
    for (int ks = 0; ks < 8; ks++) {
        const int k0 = ks * 8;
        uint32_t a[2][4], bb[4][2];
#pragma unroll
        for (int mi = 0; mi < 2; mi++) {
            int r = mi * 16 + g;
            a[mi][0] = Pw[r * AT + k0 + tg];
            a[mi][1] = Pw[(r + 8) * AT + k0 + tg];
            a[mi][2] = Pw[r * AT + k0 + tg + 4];
            a[mi][3] = Pw[(r + 8) * AT + k0 + tg + 4];
        }
#pragma unroll
        for (int ni = 0; ni < 4; ni++) {
            bb[ni][0] = Vs[(k0 + tg) * AT + ch0 + ni * 8 + g];
            bb[ni][1] = Vs[(k0 + tg + 4) * AT + ch0 + ni * 8 + g];
        }
#pragma unroll
        for (int mi = 0; mi < 2; mi++)
#pragma unroll
            for (int ni = 0; ni < 4; ni++)
                mma_tf32(acc2[mi][ni], a[mi], bb[ni]);
    }

#pragma unroll
    for (int mi = 0; mi < 2; mi++) {
        const int row = rbase + mi * 16 + g;
#pragma unroll
        for (int ni = 0; ni < 4; ni++) {
            const int col = hp * 64 + ch0 + ni * 8 + 2 * tg;
            *(float2*)(S + (size_t)(b * NTOK + row) * 256 + col) =
                make_float2(acc2[mi][ni][0], acc2[mi][ni][1]);
            *(float2*)(S + (size_t)(b * NTOK + row + 8) * 256 + col) =
                make_float2(acc2[mi][ni][2], acc2[mi][ni][3]);
        }
    }
}

// ---------------------------------------------------------------------------
// LePE depthwise 3x3 conv, accumulated into g_S. (unchanged)
// ---------------------------------------------------------------------------
__global__ __launch_bounds__(256) void lepe_kernel(
    const float* __restrict__ Q, const float* __restrict__ rw,
    const float* __restrict__ rb, float* __restrict__ S)
{
    __shared__ float sm[100][64];

    const int win = blockIdx.x;
    const int b = blockIdx.y;
    const int cb = blockIdx.z * 64;
    const int wr = win >> 5, wc = win & 31;
    const int hh0 = wr * 8, ww0 = wc * 8;
    const int t = threadIdx.x;
    const int c = t & 63, p0 = t >> 6;

    for (int p = p0; p < 100; p += 4) {
        int py = p / 10, px = p % 10;
        int hh = hh0 + py - 1, ww = ww0 + px - 1;
        float v = 0.f;
        if (hh >= 0 && hh < IMG && ww >= 0 && ww < IMG) {
            size_t idx = (((size_t)(b * NW + (hh >> 3) * 32 + (ww >> 3))) * NTOK
                          + ((hh & 7) * 8 + (ww & 7))) * (size_t)CH + cb + c;
            v = Q[idx];
        }
        sm[p][c] = v;
    }
    __syncthreads();

    float w[9];
#pragma unroll
    for (int k = 0; k < 9; k++) w[k] = rw[(cb + c) * 9 + k];
    const float bias = rb[cb + c];

    const size_t sbase = (((size_t)(b * NW + win)) * NTOK) * CH + cb + c;
    for (int p = p0; p < 64; p += 4) {
        int py = p >> 3, px = p & 7;
        float acc = bias;
#pragma unroll
        for (int dy = 0; dy < 3; dy++)
#pragma unroll
            for (int dx = 0; dx < 3; dx++)
                acc = fmaf(sm[(py + dy) * 10 + (px + dx)][c], w[dy * 3 + dx], acc);
        S[sbase + (size_t)p * CH] += acc;
    }
}

// ---------------------------------------------------------------------------
// kernel_launch
// ---------------------------------------------------------------------------
extern "C" void kernel_launch(void* const* d_in, const int* in_sizes, int n_in,
                              void* d_out, int out_size)
{
    const float* x    = (const float*)d_in[0];
    const float* y    = (const float*)d_in[1];
    const float* mask = (const float*)d_in[2];
    const float* Wq   = (const float*)d_in[3];
    const float* bq   = (const float*)d_in[4];
    const float* Wk   = (const float*)d_in[5];
    const float* bk   = (const float*)d_in[6];
    const float* Wv   = (const float*)d_in[7];
    const float* bv   = (const float*)d_in[8];
    const float* rw   = (const float*)d_in[9];
    const float* rb   = (const float*)d_in[10];
    const float* Wp   = (const float*)d_in[11];
    const float* bp   = (const float*)d_in[12];
    float* out        = (float*)d_out;

    float *pQ, *pK, *pV, *pS;
    cudaGetSymbolAddress((void**)&pQ, g_Q);
    cudaGetSymbolAddress((void**)&pK, g_K);
    cudaGetSymbolAddress((void**)&pV, g_V);
    cudaGetSymbolAddress((void**)&pS, g_S);

    static bool attr_done = false;
    if (!attr_done) {
        cudaFuncSetAttribute(gemm_mma, cudaFuncAttributeMaxDynamicSharedMemorySize, GEMM_SMEM);
        cudaFuncSetAttribute(attn_mma, cudaFuncAttributeMaxDynamicSharedMemorySize, ATTN_SMEM);
        attr_done = true;
    }

    dim3 gg(2, MTOT / 128);   // (256/128, 262144/128)
    gemm_mma<<<gg, 256, GEMM_SMEM>>>(x, Wq, bq, pQ);
    gemm_mma<<<gg, 256, GEMM_SMEM>>>(y, Wk, bk, pK);
    gemm_mma<<<gg, 256, GEMM_SMEM>>>(x, Wv, bv, pV);

    attn_mma<<<dim3(4, BWIN), 128, ATTN_SMEM>>>(pQ, pK, pV, mask, pS);

    lepe_kernel<<<dim3(NW, BATCH, 4), 256>>>(pQ, rw, rb, pS);

    gemm_mma<<<gg, 256, GEMM_SMEM>>>(pS, Wp, bp, out);
}

// round 5
// speedup vs baseline: 2.7124x; 1.0865x over previous
#include <cuda_runtime.h>
#include <cuda_bf16.h>
#include <cstdint>

// Problem constants (fixed by setup_inputs)
#define BATCH 4
#define IMG 256
#define WS 8
#define NW 1024              // (256/8)^2
#define BWIN (BATCH * NW)    // 4096 windows
#define NTOK 64              // WS*WS
#define CH 256
#define HEADS 8
#define HD 32
#define MTOT (BWIN * NTOK)   // 262144 rows

// Scratch
__device__ float g_Q[(size_t)MTOT * CH];
__device__ float g_K[(size_t)MTOT * CH];
__device__ float g_V[(size_t)MTOT * CH];
__device__ float g_S[(size_t)MTOT * CH];

// ---------------------------------------------------------------------------
// helpers (sm_80-generic; compute_103-safe)
// ---------------------------------------------------------------------------
__device__ __forceinline__ uint32_t tf32_rna(float x) {
    uint32_t y;
    asm("cvt.rna.tf32.f32 %0, %1;" : "=r"(y) : "f"(x));
    return y;
}
__device__ __forceinline__ void mma_tf32(float* d, const uint32_t* a, const uint32_t* b) {
    asm volatile(
        "mma.sync.aligned.m16n8k8.row.col.f32.tf32.tf32.f32 "
        "{%0,%1,%2,%3}, {%4,%5,%6,%7}, {%8,%9}, {%0,%1,%2,%3};"
        : "+f"(d[0]), "+f"(d[1]), "+f"(d[2]), "+f"(d[3])
        : "r"(a[0]), "r"(a[1]), "r"(a[2]), "r"(a[3]), "r"(b[0]), "r"(b[1]));
}
__device__ __forceinline__ uint32_t smem_u32(const void* p) {
    uint32_t a;
    asm("{ .reg .u64 t; cvta.to.shared.u64 t, %1; cvt.u32.u64 %0, t; }" : "=r"(a) : "l"(p));
    return a;
}
__device__ __forceinline__ void cp16(void* dst, const void* src) {
    uint32_t d = smem_u32(dst);
    asm volatile("cp.async.cg.shared.global [%0], [%1], 16;" :: "r"(d), "l"(src));
}
#define CP_COMMIT() asm volatile("cp.async.commit_group;" ::: "memory")
#define CP_WAIT1()  asm volatile("cp.async.wait_group 1;" ::: "memory")

// ---------------------------------------------------------------------------
// GEMM via mma.sync tf32, cp.async double-buffered:
// C[M x 256] = A[M x 256] @ Wt^T + bias
// Block 256 thr (8 warps, 2x4), tile 128x128x32, warp tile 64x32.
// ---------------------------------------------------------------------------
#define GP 36                               // fp32 row stride in smem (pad)
#define GEMM_SMEM (2 * 2 * 128 * GP * 4)    // 73728 B

__global__ __launch_bounds__(256) void gemm_mma(
    const float* __restrict__ A, const float* __restrict__ Wt,
    const float* __restrict__ bias, float* __restrict__ C)
{
    extern __shared__ float gsm[];
    float* As = gsm;                 // [2][128][GP]
    float* Bs = gsm + 2 * 128 * GP;  // [2][128][GP]

    const int t = threadIdx.x, lane = t & 31, warp = t >> 5;
    const int wm = warp & 1, wn = warp >> 1;         // 2 x 4 warp grid
    const int m0 = blockIdx.y * 128, n0 = blockIdx.x * 128;
    const int g = lane >> 2, tg = lane & 3;

    const int lrow = t >> 3;            // 0..31 (+32*i)
    const int lc4  = (t & 7) * 4;       // 0..28

    float acc[4][4][4];
#pragma unroll
    for (int mi = 0; mi < 4; mi++)
#pragma unroll
        for (int ni = 0; ni < 4; ni++)
#pragma unroll
            for (int r = 0; r < 4; r++) acc[mi][ni][r] = 0.f;

    // prologue: tile 0 -> buf 0
#pragma unroll
    for (int i = 0; i < 4; i++) {
        int row = lrow + i * 32;
        cp16(&As[row * GP + lc4], A  + (size_t)(m0 + row) * 256 + lc4);
        cp16(&Bs[row * GP + lc4], Wt + (size_t)(n0 + row) * 256 + lc4);
    }
    CP_COMMIT();

    for (int kc = 0; kc < 8; kc++) {
        if (kc < 7) {
            int buf = (kc + 1) & 1;
            int ko = (kc + 1) * 32;
#pragma unroll
            for (int i = 0; i < 4; i++) {
                int row = lrow + i * 32;
                cp16(&As[(buf * 128 + row) * GP + lc4], A  + (size_t)(m0 + row) * 256 + ko + lc4);
                cp16(&Bs[(buf * 128 + row) * GP + lc4], Wt + (size_t)(n0 + row) * 256 + ko + lc4);
            }
        }
        CP_COMMIT();
        CP_WAIT1();
        __syncthreads();

        const float* Ab = As + (kc & 1) * 128 * GP;
        const float* Bb = Bs + (kc & 1) * 128 * GP;
#pragma unroll
        for (int ks = 0; ks < 4; ks++) {
            const int k0 = ks * 8;
            uint32_t a[4][4], b[4][2];
#pragma unroll
            for (int mi = 0; mi < 4; mi++) {
                int r = wm * 64 + mi * 16 + g;
                a[mi][0] = tf32_rna(Ab[r * GP + k0 + tg]);
                a[mi][1] = tf32_rna(Ab[(r + 8) * GP + k0 + tg]);
                a[mi][2] = tf32_rna(Ab[r * GP + k0 + tg + 4]);
                a[mi][3] = tf32_rna(Ab[(r + 8) * GP + k0 + tg + 4]);
            }
#pragma unroll
            for (int ni = 0; ni < 4; ni++) {
                int r = wn * 32 + ni * 8 + g;
                b[ni][0] = tf32_rna(Bb[r * GP + k0 + tg]);
                b[ni][1] = tf32_rna(Bb[r * GP + k0 + tg + 4]);
            }
#pragma unroll
            for (int mi = 0; mi < 4; mi++)
#pragma unroll
                for (int ni = 0; ni < 4; ni++)
                    mma_tf32(acc[mi][ni], a[mi], b[ni]);
        }
        __syncthreads();
    }

    float bv[4][2];
#pragma unroll
    for (int ni = 0; ni < 4; ni++) {
        int col = n0 + wn * 32 + ni * 8 + 2 * tg;
        bv[ni][0] = __ldg(bias + col);
        bv[ni][1] = __ldg(bias + col + 1);
    }
#pragma unroll
    for (int mi = 0; mi < 4; mi++) {
        int r0 = m0 + wm * 64 + mi * 16 + g;
#pragma unroll
        for (int ni = 0; ni < 4; ni++) {
            int col = n0 + wn * 32 + ni * 8 + 2 * tg;
            *(float2*)(C + (size_t)r0 * 256 + col) =
                make_float2(acc[mi][ni][0] + bv[ni][0], acc[mi][ni][1] + bv[ni][1]);
            *(float2*)(C + (size_t)(r0 + 8) * 256 + col) =
                make_float2(acc[mi][ni][2] + bv[ni][0], acc[mi][ni][3] + bv[ni][1]);
        }
    }
}

// ---------------------------------------------------------------------------
// Attention via mma.sync tf32. Block = 128 thr (4 warps) per (window, head-pair).
// Warp w: head = hp*2 + (w>>1), rows 32*(w&1)..+31.
// smem: Qs/Ks/Vs [64][68] tf32 bits. P tiles ALIAS the Q/K region (Q/K are
// dead after the score MMAs; a CTA barrier separates the phases).
// 52.2 KB smem -> 4 CTAs/SM (25% occ) vs previous 87 KB -> 2 CTAs (12%).
// ---------------------------------------------------------------------------
#define AT 68
#define ATTN_SMEM (3 * 64 * AT * 4)   // 52224 B

__global__ __launch_bounds__(128) void attn_mma(
    const float* __restrict__ Q, const float* __restrict__ K,
    const float* __restrict__ V, const float* __restrict__ mask,
    float* __restrict__ S)
{
    extern __shared__ uint32_t sm[];
    uint32_t* Qs = sm;                       // [64][AT]
    uint32_t* Ks = sm + 64 * AT;
    uint32_t* Vs = sm + 2 * 64 * AT;
    uint32_t* Ps = sm;                       // [4][32][AT] — aliases Qs+Ks (8704 words)

    const int hp = blockIdx.x;      // 0..3 head-pair
    const int b  = blockIdx.y;      // 0..4095
    const int t = threadIdx.x, lane = t & 31, w = t >> 5;
    const int g = lane >> 2, tg = lane & 3;
    const size_t base = (size_t)b * NTOK * CH + hp * 64;
    const float scale = 0.17677669529663687f; // 32^-0.5

    // stage Q (scaled), K, V channel slice as tf32
#pragma unroll
    for (int i = 0; i < 8; i++) {
        int idx = i * 128 + t;
        int row = idx >> 4;            // 0..63
        int cq  = (idx & 15) * 4;      // 0..60
        const float4 q4 = *(const float4*)(Q + base + (size_t)row * 256 + cq);
        const float4 k4 = *(const float4*)(K + base + (size_t)row * 256 + cq);
        const float4 v4 = *(const float4*)(V + base + (size_t)row * 256 + cq);
        uint32_t* qp = Qs + row * AT + cq;
        qp[0] = tf32_rna(q4.x * scale); qp[1] = tf32_rna(q4.y * scale);
        qp[2] = tf32_rna(q4.z * scale); qp[3] = tf32_rna(q4.w * scale);
        uint32_t* kp = Ks + row * AT + cq;
        kp[0] = tf32_rna(k4.x); kp[1] = tf32_rna(k4.y);
        kp[2] = tf32_rna(k4.z); kp[3] = tf32_rna(k4.w);
        uint32_t* vp = Vs + row * AT + cq;
        vp[0] = tf32_rna(v4.x); vp[1] = tf32_rna(v4.y);
        vp[2] = tf32_rna(v4.z); vp[3] = tf32_rna(v4.w);
    }
    __syncthreads();

    const int ch0 = (w >> 1) * 32;    // head channel offset within slice
    const int rbase = (w & 1) * 32;   // token-row base

    // scores: acc[mi][ni][4], rows rbase+mi*16+{g,g+8}, cols ni*8+2tg+{0,1}
    float acc[2][8][4];
#pragma unroll
    for (int mi = 0; mi < 2; mi++)
#pragma unroll
        for (int ni = 0; ni < 8; ni++)
#pragma unroll
            for (int r = 0; r < 4; r++) acc[mi][ni][r] = 0.f;

#pragma unroll
    for (int ks = 0; ks < 4; ks++) {
        const int k0 = ch0 + ks * 8;
        uint32_t a[2][4], bb[8][2];
#pragma unroll
        for (int mi = 0; mi < 2; mi++) {
            int r = rbase + mi * 16 + g;
            a[mi][0] = Qs[r * AT + k0 + tg];
            a[mi][1] = Qs[(r + 8) * AT + k0 + tg];
            a[mi][2] = Qs[r * AT + k0 + tg + 4];
            a[mi][3] = Qs[(r + 8) * AT + k0 + tg + 4];
        }
#pragma unroll
        for (int ni = 0; ni < 8; ni++) {
            int r = ni * 8 + g;
            bb[ni][0] = Ks[r * AT + k0 + tg];
            bb[ni][1] = Ks[r * AT + k0 + tg + 4];
        }
#pragma unroll
        for (int mi = 0; mi < 2; mi++)
#pragma unroll
            for (int ni = 0; ni < 8; ni++)
                mma_tf32(acc[mi][ni], a[mi], bb[ni]);
    }

    // Q/K fragments fully consumed -> safe to recycle their smem for P.
    __syncthreads();

    // mask + softmax (register-resident, quad shuffles), write P to smem as tf32
    const float* mp = mask + (size_t)(b & (NW - 1)) * NTOK * NTOK;
#pragma unroll
    for (int mi = 0; mi < 2; mi++) {
#pragma unroll
        for (int half = 0; half < 2; half++) {
            const int row = rbase + mi * 16 + half * 8 + g;
            const int o = half * 2;
            float v[8][2];
            float mx = -1e30f;
#pragma unroll
            for (int ni = 0; ni < 8; ni++) {
                float2 mv = *(const float2*)(mp + row * 64 + ni * 8 + 2 * tg);
                v[ni][0] = acc[mi][ni][o] + mv.x;
                v[ni][1] = acc[mi][ni][o + 1] + mv.y;
                mx = fmaxf(mx, fmaxf(v[ni][0], v[ni][1]));
            }
            mx = fmaxf(mx, __shfl_xor_sync(0xffffffffu, mx, 1));
            mx = fmaxf(mx, __shfl_xor_sync(0xffffffffu, mx, 2));
            float sum = 0.f;
#pragma unroll
            for (int ni = 0; ni < 8; ni++) {
                v[ni][0] = __expf(v[ni][0] - mx);
                v[ni][1] = __expf(v[ni][1] - mx);
                sum += v[ni][0] + v[ni][1];
            }
            sum += __shfl_xor_sync(0xffffffffu, sum, 1);
            sum += __shfl_xor_sync(0xffffffffu, sum, 2);
            const float inv = 1.f / sum;
            uint32_t* pp = Ps + (w * 32 + mi * 16 + half * 8 + g) * AT;
#pragma unroll
            for (int ni = 0; ni < 8; ni++) {
                pp[ni * 8 + 2 * tg]     = tf32_rna(v[ni][0] * inv);
                pp[ni * 8 + 2 * tg + 1] = tf32_rna(v[ni][1] * inv);
            }
        }
    }
    __syncwarp();

    // O = P @ V  (k = 64 tokens, n = 32 channels)
    float acc2[2][4][4];
#pragma unroll
    for (int mi = 0; mi < 2; mi++)
#pragma unroll
        for (int ni = 0; ni < 4; ni++)
#pragma unroll
            for (int r = 0; r < 4; r++) acc2[mi][ni][r] = 0.f;

    const uint32_t* Pw = Ps + w * 32 * AT;
#pragma unroll
    for (int ks = 0; ks < 8; ks++) {
        const int k0 = ks * 8;
        uint32_t a[2][4], bb[4][2];
#pragma unroll
        for (int mi = 0; mi < 2; mi++) {
            int r = mi * 16 + g;
            a[mi][0] = Pw[r * AT + k0 + tg];
            a[mi][1] = Pw[(r + 8) * AT + k0 + tg];
            a[mi][2] = Pw[r * AT + k0 + tg + 4];
            a[mi][3] = Pw[(r + 8) * AT + k0 + tg + 4];
        }
#pragma unroll
        for (int ni = 0; ni < 4; ni++) {
            bb[ni][0] = Vs[(k0 + tg) * AT + ch0 + ni * 8 + g];
            bb[ni][1] = Vs[(k0 + tg + 4) * AT + ch0 + ni * 8 + g];
        }
#pragma unroll
        for (int mi = 0; mi < 2; mi++)
#pragma unroll
            for (int ni = 0; ni < 4; ni++)
                mma_tf32(acc2[mi][ni], a[mi], bb[ni]);
    }

#pragma unroll
    for (int mi = 0; mi < 2; mi++) {
        const int row = rbase + mi * 16 + g;
#pragma unroll
        for (int ni = 0; ni < 4; ni++) {
            const int col = hp * 64 + ch0 + ni * 8 + 2 * tg;
            *(float2*)(S + (size_t)(b * NTOK + row) * 256 + col) =
                make_float2(acc2[mi][ni][0], acc2[mi][ni][1]);
            *(float2*)(S + (size_t)(b * NTOK + row + 8) * 256 + col) =
                make_float2(acc2[mi][ni][2], acc2[mi][ni][3]);
        }
    }
}

// ---------------------------------------------------------------------------
// LePE depthwise 3x3 conv, accumulated into g_S. (unchanged)
// ---------------------------------------------------------------------------
__global__ __launch_bounds__(256) void lepe_kernel(
    const float* __restrict__ Q, const float* __restrict__ rw,
    const float* __restrict__ rb, float* __restrict__ S)
{
    __shared__ float sm[100][64];

    const int win = blockIdx.x;
    const int b = blockIdx.y;
    const int cb = blockIdx.z * 64;
    const int wr = win >> 5, wc = win & 31;
    const int hh0 = wr * 8, ww0 = wc * 8;
    const int t = threadIdx.x;
    const int c = t & 63, p0 = t >> 6;

    for (int p = p0; p < 100; p += 4) {
        int py = p / 10, px = p % 10;
        int hh = hh0 + py - 1, ww = ww0 + px - 1;
        float v = 0.f;
        if (hh >= 0 && hh < IMG && ww >= 0 && ww < IMG) {
            size_t idx = (((size_t)(b * NW + (hh >> 3) * 32 + (ww >> 3))) * NTOK
                          + ((hh & 7) * 8 + (ww & 7))) * (size_t)CH + cb + c;
            v = Q[idx];
        }
        sm[p][c] = v;
    }
    __syncthreads();

    float w[9];
#pragma unroll
    for (int k = 0; k < 9; k++) w[k] = rw[(cb + c) * 9 + k];
    const float bias = rb[cb + c];

    const size_t sbase = (((size_t)(b * NW + win)) * NTOK) * CH + cb + c;
    for (int p = p0; p < 64; p += 4) {
        int py = p >> 3, px = p & 7;
        float acc = bias;
#pragma unroll
        for (int dy = 0; dy < 3; dy++)
#pragma unroll
            for (int dx = 0; dx < 3; dx++)
                acc = fmaf(sm[(py + dy) * 10 + (px + dx)][c], w[dy * 3 + dx], acc);
        S[sbase + (size_t)p * CH] += acc;
    }
}

// ---------------------------------------------------------------------------
// kernel_launch
// ---------------------------------------------------------------------------
extern "C" void kernel_launch(void* const* d_in, const int* in_sizes, int n_in,
                              void* d_out, int out_size)
{
    const float* x    = (const float*)d_in[0];
    const float* y    = (const float*)d_in[1];
    const float* mask = (const float*)d_in[2];
    const float* Wq   = (const float*)d_in[3];
    const float* bq   = (const float*)d_in[4];
    const float* Wk   = (const float*)d_in[5];
    const float* bk   = (const float*)d_in[6];
    const float* Wv   = (const float*)d_in[7];
    const float* bv   = (const float*)d_in[8];
    const float* rw   = (const float*)d_in[9];
    const float* rb   = (const float*)d_in[10];
    const float* Wp   = (const float*)d_in[11];
    const float* bp   = (const float*)d_in[12];
    float* out        = (float*)d_out;

    float *pQ, *pK, *pV, *pS;
    cudaGetSymbolAddress((void**)&pQ, g_Q);
    cudaGetSymbolAddress((void**)&pK, g_K);
    cudaGetSymbolAddress((void**)&pV, g_V);
    cudaGetSymbolAddress((void**)&pS, g_S);

    static bool attr_done = false;
    if (!attr_done) {
        cudaFuncSetAttribute(gemm_mma, cudaFuncAttributeMaxDynamicSharedMemorySize, GEMM_SMEM);
        cudaFuncSetAttribute(attn_mma, cudaFuncAttributeMaxDynamicSharedMemorySize, ATTN_SMEM);
        attr_done = true;
    }

    dim3 gg(2, MTOT / 128);   // (256/128, 262144/128)
    gemm_mma<<<gg, 256, GEMM_SMEM>>>(x, Wq, bq, pQ);
    gemm_mma<<<gg, 256, GEMM_SMEM>>>(y, Wk, bk, pK);
    gemm_mma<<<gg, 256, GEMM_SMEM>>>(x, Wv, bv, pV);

    attn_mma<<<dim3(4, BWIN), 128, ATTN_SMEM>>>(pQ, pK, pV, mask, pS);

    lepe_kernel<<<dim3(NW, BATCH, 4), 256>>>(pQ, rw, rb, pS);

    gemm_mma<<<gg, 256, GEMM_SMEM>>>(pS, Wp, bp, out);
}